// round 16
// baseline (speedup 1.0000x reference)
#include <cuda_runtime.h>
#include <cuda_bf16.h>
#include <cstdint>

// ============================================================================
// FusedLinearCrossEntropy on GB300, portable tensor path (compute_103):
// bf16 ldmatrix + mma.sync.m16n8k16, cp.async 3-stage, 128x128 tile,
// 128 threads, 2 CTAs/SM, ks fragment double buffering (R13 schedule) with
// the ks+1 ldsm burst split and interleaved into the mma stream (MIO spread).
// Fused prep kernel: converts first, then exact target logits.
// loss = mean(lse - tgt_logit + 1e-4*lse^2), z_loss = mean(1e-4*lse^2)
// ============================================================================

#define BM 128
#define BN 128
#define BK 64           // bf16 per K-slab = 128 bytes/row
#define STAGES 3
#define GEMM_THREADS 128
#define LSE_SQ_SCALE 1e-4f

#define MAX_N 4096
#define MAX_D 2048
#define MAX_VPAD 50432
#define MAX_NVT 400

// -------- scratch (device globals: no allocs allowed) --------
__device__ __nv_bfloat16 g_A[(size_t)MAX_N * MAX_D];       // ~16.8 MB
__device__ __nv_bfloat16 g_W[(size_t)MAX_VPAD * MAX_D];    // ~206.6 MB
__device__ float g_part[(size_t)MAX_NVT * MAX_N];
__device__ float g_tgt[MAX_N];
__device__ float g_tok[MAX_N];
__device__ float g_zz[MAX_N];

// -------- helpers --------
__device__ __forceinline__ uint32_t smem_to_u32(const void* p) {
    uint32_t a;
    asm("{ .reg .u64 t; cvta.to.shared.u64 t, %1; cvt.u32.u64 %0, t; }" : "=r"(a) : "l"(p));
    return a;
}

// pack two fp32 into bf16x2 (lo -> low 16 bits, hi -> high 16 bits)
__device__ __forceinline__ uint32_t pack_bf16x2(float lo, float hi) {
    uint32_t r;
    asm("cvt.rn.bf16x2.f32 %0, %1, %2;" : "=r"(r) : "f"(hi), "f"(lo));
    return r;
}

__device__ __forceinline__ void cp_async16(uint32_t saddr, const void* gaddr) {
    asm volatile("cp.async.cg.shared.global [%0], [%1], 16;" :: "r"(saddr), "l"(gaddr));
}
#define CP_COMMIT() asm volatile("cp.async.commit_group;" ::: "memory")
#define CP_WAIT(n)  asm volatile("cp.async.wait_group %0;" :: "n"(n) : "memory")

__device__ __forceinline__ void ldsm_x4(uint32_t& r0, uint32_t& r1, uint32_t& r2, uint32_t& r3,
                                        uint32_t addr) {
    asm volatile("ldmatrix.sync.aligned.m8n8.x4.shared.b16 {%0,%1,%2,%3}, [%4];"
                 : "=r"(r0), "=r"(r1), "=r"(r2), "=r"(r3) : "r"(addr));
}

__device__ __forceinline__ void mma_16816(float* c, const uint32_t* a, const uint32_t* b) {
    asm volatile("mma.sync.aligned.m16n8k16.row.col.f32.bf16.bf16.f32 "
                 "{%0,%1,%2,%3}, {%4,%5,%6,%7}, {%8,%9}, {%0,%1,%2,%3};"
                 : "+f"(c[0]), "+f"(c[1]), "+f"(c[2]), "+f"(c[3])
                 : "r"(a[0]), "r"(a[1]), "r"(a[2]), "r"(a[3]), "r"(b[0]), "r"(b[1]));
}

// smem per CTA: 3 stages x (A 16KB + B 16KB) + rowsum[2][128]
#define STAGE_BYTES (BM * 128 + BN * 128)            // 32768
#define SM_A(s) ((s) * STAGE_BYTES)
#define SM_B(s) ((s) * STAGE_BYTES + BM * 128)
#define SM_ROWSUM (STAGES * STAGE_BYTES)             // 98304
#define SMEM_TOTAL (SM_ROWSUM + 2 * BM * 4)          // 99328 (x2 CTAs <= 228KB)

// ============================================================================
// fused prep kernel: [weight-convert | input-convert | tgt blocks]
// ============================================================================
__global__ void k_prep(const float* __restrict__ input, const float* __restrict__ weight,
                       const float* __restrict__ bias, const int* __restrict__ target,
                       int Ntok, int D, int V,
                       int nb_w, int nb_in, long real8, long pad8, long n8) {
    const int blk = blockIdx.x;
    const int tid = threadIdx.x;

    if (blk < nb_w) {
        // ---- weight fp32 -> bf16 (zero-padded rows) ----
        long i = (long)blk * 256 + tid;
        if (i >= pad8) return;
        float4 v0 = make_float4(0.f, 0.f, 0.f, 0.f), v1 = v0;
        if (i < real8) {
            v0 = reinterpret_cast<const float4*>(weight)[i * 2];
            v1 = reinterpret_cast<const float4*>(weight)[i * 2 + 1];
        }
        uint4 o;
        o.x = pack_bf16x2(v0.x, v0.y);
        o.y = pack_bf16x2(v0.z, v0.w);
        o.z = pack_bf16x2(v1.x, v1.y);
        o.w = pack_bf16x2(v1.z, v1.w);
        reinterpret_cast<uint4*>(g_W)[i] = o;
    } else if (blk < nb_w + nb_in) {
        // ---- input fp32 -> bf16 ----
        long i = (long)(blk - nb_w) * 256 + tid;
        if (i >= n8) return;
        const float4 v0 = reinterpret_cast<const float4*>(input)[i * 2];
        const float4 v1 = reinterpret_cast<const float4*>(input)[i * 2 + 1];
        uint4 o;
        o.x = pack_bf16x2(v0.x, v0.y);
        o.y = pack_bf16x2(v0.z, v0.w);
        o.z = pack_bf16x2(v1.x, v1.y);
        o.w = pack_bf16x2(v1.z, v1.w);
        reinterpret_cast<uint4*>(g_A)[i] = o;
    } else {
        // ---- exact fp32 target logit, 1 warp per token ----
        int warp = (blk - nb_w - nb_in) * 8 + (tid >> 5);
        int lane = tid & 31;
        if (warp >= Ntok) return;
        int t = target[warp];
        bool valid = (t >= 0 && t < V);
        float s = 0.f;
        if (valid) {
            const float* a = input + (long)warp * D;
            const float* b = weight + (long)t * D;
            for (int k = lane * 4; k < D; k += 128) {
                float4 va = *reinterpret_cast<const float4*>(a + k);
                float4 vb = *reinterpret_cast<const float4*>(b + k);
                s = fmaf(va.x, vb.x, s); s = fmaf(va.y, vb.y, s);
                s = fmaf(va.z, vb.z, s); s = fmaf(va.w, vb.w, s);
            }
        }
        #pragma unroll
        for (int o = 16; o; o >>= 1) s += __shfl_xor_sync(0xffffffffu, s, o);
        if (lane == 0) g_tgt[warp] = valid ? (s + bias[t]) : 0.f;
    }
}

// ============================================================================
// GEMM (128x128 CTA tile, 4 warps, 2 CTAs/SM) + fused sum(exp(logit+bias))
// R13 schedule + interleaved ks+1 ldsm (A-half, 16 mma, B-half, 16 mma)
// ============================================================================
__global__ void __launch_bounds__(GEMM_THREADS, 2)
k_gemm_lse(const float* __restrict__ bias, int Ntok, int D, int V) {
    extern __shared__ char smem[];
    const uint32_t sb = smem_to_u32(smem);
    const int tid = threadIdx.x;
    const int wid = tid >> 5;
    const int g   = tid & 31;
    const int mw  = wid >> 1;       // 0..1
    const int nw  = wid & 1;        // 0..1
    const int mbase = mw * 64;
    const int nbase = nw * 64;
    const int m0 = blockIdx.x * BM;
    const int vt = blockIdx.y;
    const int v0 = vt * BN;
    const int T = D / BK;           // 32

    // ---- hoisted load addressing ----
    const int ld_row = tid >> 3;                 // 0..15
    const int ld_c   = tid & 7;
    const __nv_bfloat16* aptr = g_A + (long)(m0 + ld_row) * D + ld_c * 8;
    const __nv_bfloat16* bptr = g_W + (long)(v0 + ld_row) * D + ld_c * 8;
    const long ld_stride = 16 * (long)D;
    const uint32_t ld_soff = (uint32_t)(ld_row * 128 + ((ld_c * 16) ^ ((ld_row & 7) << 4)));

    auto load_stage = [&](int s) {
        const uint32_t sa = sb + SM_A(s) + ld_soff;
        const uint32_t sB = sb + SM_B(s) + ld_soff;
        #pragma unroll
        for (int i = 0; i < 8; i++) cp_async16(sa + i * 2048, aptr + i * ld_stride);
        #pragma unroll
        for (int i = 0; i < 8; i++) cp_async16(sB + i * 2048, bptr + i * ld_stride);
    };

    float acc[4][8][4];
    #pragma unroll
    for (int mi = 0; mi < 4; mi++)
        #pragma unroll
        for (int ni = 0; ni < 8; ni++)
            #pragma unroll
            for (int j = 0; j < 4; j++) acc[mi][ni][j] = 0.f;

    const int a_row_lo = g & 15;
    const int a_kxor = (g >> 4) << 4;
    const int b_row_lo = ((g >> 4) << 3) + (g & 7);
    const int b_kxor = (g & 8) << 1;

    const uint32_t a_row_off = (uint32_t)((mbase + a_row_lo) * 128);
    const uint32_t b_row_off = (uint32_t)((nbase + b_row_lo) * 128);
    const uint32_t a_xorv = (uint32_t)(((mbase + a_row_lo) & 7) << 4);
    const uint32_t b_xorv = (uint32_t)(((nbase + b_row_lo) & 7) << 4);

    uint32_t a_kp[4], b_kp[4];
    #pragma unroll
    for (int ks = 0; ks < 4; ks++) {
        a_kp[ks] = (((uint32_t)(ks * 32) + (uint32_t)a_kxor) ^ a_xorv);
        b_kp[ks] = (((uint32_t)(ks * 32) + (uint32_t)b_kxor) ^ b_xorv);
    }

    #pragma unroll
    for (int s = 0; s < STAGES - 1; s++) { load_stage(s); CP_COMMIT(); aptr += BK; bptr += BK; }

    uint32_t a[2][4][4], b[2][4][4];   // ks double buffer

    for (int t = 0; t < T; t++) {
        CP_WAIT(1);
        __syncthreads();
        const int s = t % STAGES;
        const uint32_t abase = sb + SM_A(s) + a_row_off;
        const uint32_t bbase = sb + SM_B(s) + b_row_off;

        // prime ks=0 fragments FIRST (their stage is complete per CP_WAIT) ...
        #pragma unroll
        for (int mi = 0; mi < 4; mi++)
            ldsm_x4(a[0][mi][0], a[0][mi][1], a[0][mi][2], a[0][mi][3],
                    abase + mi * 2048 + a_kp[0]);
        #pragma unroll
        for (int np = 0; np < 4; np++)
            ldsm_x4(b[0][np][0], b[0][np][1], b[0][np][2], b[0][np][3],
                    bbase + np * 2048 + b_kp[0]);

        // ... then the cp.async burst drains under the ks=0/1 mma stream
        if (t + STAGES - 1 < T) { load_stage((t + STAGES - 1) % STAGES); aptr += BK; bptr += BK; }
        CP_COMMIT();

        #pragma unroll
        for (int ks = 0; ks < 4; ks++) {
            const int cur = ks & 1, nxt = cur ^ 1;
            // first half of ks+1 refill (A), spread before the first mma half
            if (ks < 3) {
                #pragma unroll
                for (int mi = 0; mi < 4; mi++)
                    ldsm_x4(a[nxt][mi][0], a[nxt][mi][1], a[nxt][mi][2], a[nxt][mi][3],
                            abase + mi * 2048 + a_kp[ks + 1]);
            }
            // mma half 1: mi = 0,1
            #pragma unroll
            for (int mi = 0; mi < 2; mi++)
                #pragma unroll
                for (int ni = 0; ni < 8; ni++)
                    mma_16816(acc[mi][ni], a[cur][mi], &b[cur][ni >> 1][(ni & 1) * 2]);
            // second half of ks+1 refill (B)
            if (ks < 3) {
                #pragma unroll
                for (int np = 0; np < 4; np++)
                    ldsm_x4(b[nxt][np][0], b[nxt][np][1], b[nxt][np][2], b[nxt][np][3],
                            bbase + np * 2048 + b_kp[ks + 1]);
            }
            // mma half 2: mi = 2,3
            #pragma unroll
            for (int mi = 2; mi < 4; mi++)
                #pragma unroll
                for (int ni = 0; ni < 8; ni++)
                    mma_16816(acc[mi][ni], a[cur][mi], &b[cur][ni >> 1][(ni & 1) * 2]);
        }
    }
    __syncthreads();

    // ---- epilogue: per-row sum(exp(logit + bias)) ----
    float* rowsum = reinterpret_cast<float*>(smem + SM_ROWSUM);
    if (v0 + BN <= V) {
        float bb[16];
        #pragma unroll
        for (int ni = 0; ni < 8; ni++) {
            int col = v0 + nbase + ni * 8 + (g & 3) * 2;
            bb[ni * 2]     = bias[col];
            bb[ni * 2 + 1] = bias[col + 1];
        }
        #pragma unroll
        for (int mi = 0; mi < 4; mi++) {
            float s0 = 0.f, s1 = 0.f;
            #pragma unroll
            for (int ni = 0; ni < 8; ni++) {
                s0 += __expf(acc[mi][ni][0] + bb[ni * 2]);
                s0 += __expf(acc[mi][ni][1] + bb[ni * 2 + 1]);
                s1 += __expf(acc[mi][ni][2] + bb[ni * 2]);
                s1 += __expf(acc[mi][ni][3] + bb[ni * 2 + 1]);
            }
            s0 += __shfl_xor_sync(0xffffffffu, s0, 1); s0 += __shfl_xor_sync(0xffffffffu, s0, 2);
            s1 += __shfl_xor_sync(0xffffffffu, s1, 1); s1 += __shfl_xor_sync(0xffffffffu, s1, 2);
            if ((g & 3) == 0) {
                int r = mbase + mi * 16 + (g >> 2);
                rowsum[nw * BM + r]     = s0;
                rowsum[nw * BM + r + 8] = s1;
            }
        }
    } else {
        #pragma unroll
        for (int mi = 0; mi < 4; mi++) {
            float s0 = 0.f, s1 = 0.f;
            #pragma unroll
            for (int ni = 0; ni < 8; ni++) {
                int col = v0 + nbase + ni * 8 + (g & 3) * 2;
                float b0 = (col < V)     ? bias[col]     : 0.f;
                float b1 = (col + 1 < V) ? bias[col + 1] : 0.f;
                if (col < V)     { s0 += __expf(acc[mi][ni][0] + b0); s1 += __expf(acc[mi][ni][2] + b0); }
                if (col + 1 < V) { s0 += __expf(acc[mi][ni][1] + b1); s1 += __expf(acc[mi][ni][3] + b1); }
            }
            s0 += __shfl_xor_sync(0xffffffffu, s0, 1); s0 += __shfl_xor_sync(0xffffffffu, s0, 2);
            s1 += __shfl_xor_sync(0xffffffffu, s1, 1); s1 += __shfl_xor_sync(0xffffffffu, s1, 2);
            if ((g & 3) == 0) {
                int r = mbase + mi * 16 + (g >> 2);
                rowsum[nw * BM + r]     = s0;
                rowsum[nw * BM + r + 8] = s1;
            }
        }
    }
    __syncthreads();
    if (tid < BM) {
        float tot = rowsum[tid] + rowsum[BM + tid];
        g_part[(size_t)vt * Ntok + (m0 + tid)] = tot;
    }
}

// ============================================================================
// per-row reduce: lse, ce, z
// ============================================================================
__global__ void k_row_reduce(const int* __restrict__ target, int Ntok, int NVT, int V) {
    int r = blockIdx.x * blockDim.x + threadIdx.x;
    if (r >= Ntok) return;
    float s = 0.f;
    for (int i = 0; i < NVT; i++) s += g_part[(size_t)i * Ntok + r];
    float lse = logf(s);
    int t = target[r];
    bool valid = (t >= 0 && t < V);
    float z = LSE_SQ_SCALE * lse * lse;
    g_tok[r] = valid ? (lse - g_tgt[r] + z) : 0.f;
    g_zz[r]  = valid ? z : 0.f;
}

// ============================================================================
// final scalar reduce
// ============================================================================
__global__ void k_final(const int* __restrict__ target, float* __restrict__ out,
                        int Ntok, int V, int out_size) {
    __shared__ float s1[1024], s2[1024];
    __shared__ int s3[1024];
    int tid = threadIdx.x;
    float a = 0.f, b = 0.f; int c = 0;
    for (int i = tid; i < Ntok; i += blockDim.x) {
        a += g_tok[i];
        b += g_zz[i];
        int t = target[i];
        c += (t >= 0 && t < V) ? 1 : 0;
    }
    s1[tid] = a; s2[tid] = b; s3[tid] = c;
    __syncthreads();
    for (int o = blockDim.x >> 1; o; o >>= 1) {
        if (tid < o) { s1[tid] += s1[tid + o]; s2[tid] += s2[tid + o]; s3[tid] += s3[tid + o]; }
        __syncthreads();
    }
    if (tid == 0) {
        float nv = (float)(s3[0] > 0 ? s3[0] : 1);
        out[0] = s1[0] / nv;
        if (out_size > 1) out[1] = s2[0] / nv;
    }
}

// ============================================================================
extern "C" void kernel_launch(void* const* d_in, const int* in_sizes, int n_in,
                              void* d_out, int out_size) {
    const float* input = (const float*)d_in[0];
    const float* weight = (const float*)d_in[1];
    const float* bias = (const float*)d_in[2];
    const int* target = (const int*)d_in[3];

    const int V = in_sizes[2];
    const int Ntok = in_sizes[3];
    const int D = in_sizes[0] / Ntok;
    const int NVT = (V + BN - 1) / BN;     // 393
    const long Vpad = (long)NVT * BN;      // 50304

    // 1. fused prep: fp32->bf16 converts (first) + exact target logits (last)
    {
        long n8 = (long)Ntok * D / 8;
        long real8 = (long)V * D / 8;
        long pad8 = Vpad * D / 8;
        int nb_w = (int)((pad8 + 255) / 256);
        int nb_in = (int)((n8 + 255) / 256);
        int nb_tgt = (Ntok + 7) / 8;
        k_prep<<<nb_w + nb_in + nb_tgt, 256>>>(input, weight, bias, target,
                                               Ntok, D, V, nb_w, nb_in, real8, pad8, n8);
    }

    // 2. GEMM + fused sum-exp
    {
        cudaFuncSetAttribute(k_gemm_lse, cudaFuncAttributeMaxDynamicSharedMemorySize, SMEM_TOTAL);
        dim3 grid(Ntok / BM, NVT);
        k_gemm_lse<<<grid, GEMM_THREADS, SMEM_TOTAL>>>(bias, Ntok, D, V);
    }

    // 3. per-row reduce
    k_row_reduce<<<(Ntok + 127) / 128, 128>>>(target, Ntok, NVT, V);

    // 4. final scalars
    k_final<<<1, 1024>>>(target, (float*)d_out, Ntok, V, out_size);
}

// round 17
// speedup vs baseline: 1.0298x; 1.0298x over previous
#include <cuda_runtime.h>
#include <cuda_bf16.h>
#include <cstdint>

// ============================================================================
// FusedLinearCrossEntropy on GB300, portable tensor path (compute_103):
// bf16 ldmatrix + mma.sync.m16n8k16, cp.async 3-stage, 128x128 tile,
// 128 threads, 2 CTAs/SM (R13/R15 mainloop schedule — local optimum).
// Target logit extracted from the GEMM accumulators (no separate fp32 pass).
// loss = mean(lse - tgt_logit + 1e-4*lse^2), z_loss = mean(1e-4*lse^2)
// ============================================================================

#define BM 128
#define BN 128
#define BK 64           // bf16 per K-slab = 128 bytes/row
#define STAGES 3
#define GEMM_THREADS 128
#define LSE_SQ_SCALE 1e-4f

#define MAX_N 4096
#define MAX_D 2048
#define MAX_VPAD 50432
#define MAX_NVT 400

// -------- scratch (device globals: no allocs allowed) --------
__device__ __nv_bfloat16 g_A[(size_t)MAX_N * MAX_D];       // ~16.8 MB
__device__ __nv_bfloat16 g_W[(size_t)MAX_VPAD * MAX_D];    // ~206.6 MB
__device__ float g_part[(size_t)MAX_NVT * MAX_N];
__device__ float g_tgt[MAX_N];
__device__ float g_tok[MAX_N];
__device__ float g_zz[MAX_N];

// -------- helpers --------
__device__ __forceinline__ uint32_t smem_to_u32(const void* p) {
    uint32_t a;
    asm("{ .reg .u64 t; cvta.to.shared.u64 t, %1; cvt.u32.u64 %0, t; }" : "=r"(a) : "l"(p));
    return a;
}

// pack two fp32 into bf16x2 (lo -> low 16 bits, hi -> high 16 bits)
__device__ __forceinline__ uint32_t pack_bf16x2(float lo, float hi) {
    uint32_t r;
    asm("cvt.rn.bf16x2.f32 %0, %1, %2;" : "=r"(r) : "f"(hi), "f"(lo));
    return r;
}

__device__ __forceinline__ void cp_async16(uint32_t saddr, const void* gaddr) {
    asm volatile("cp.async.cg.shared.global [%0], [%1], 16;" :: "r"(saddr), "l"(gaddr));
}
#define CP_COMMIT() asm volatile("cp.async.commit_group;" ::: "memory")
#define CP_WAIT(n)  asm volatile("cp.async.wait_group %0;" :: "n"(n) : "memory")

__device__ __forceinline__ void ldsm_x4(uint32_t& r0, uint32_t& r1, uint32_t& r2, uint32_t& r3,
                                        uint32_t addr) {
    asm volatile("ldmatrix.sync.aligned.m8n8.x4.shared.b16 {%0,%1,%2,%3}, [%4];"
                 : "=r"(r0), "=r"(r1), "=r"(r2), "=r"(r3) : "r"(addr));
}

__device__ __forceinline__ void mma_16816(float* c, const uint32_t* a, const uint32_t* b) {
    asm volatile("mma.sync.aligned.m16n8k16.row.col.f32.bf16.bf16.f32 "
                 "{%0,%1,%2,%3}, {%4,%5,%6,%7}, {%8,%9}, {%0,%1,%2,%3};"
                 : "+f"(c[0]), "+f"(c[1]), "+f"(c[2]), "+f"(c[3])
                 : "r"(a[0]), "r"(a[1]), "r"(a[2]), "r"(a[3]), "r"(b[0]), "r"(b[1]));
}

// smem per CTA: 3 stages x (A 16KB + B 16KB) + rowsum[2][128]
#define STAGE_BYTES (BM * 128 + BN * 128)            // 32768
#define SM_A(s) ((s) * STAGE_BYTES)
#define SM_B(s) ((s) * STAGE_BYTES + BM * 128)
#define SM_ROWSUM (STAGES * STAGE_BYTES)             // 98304
#define SMEM_TOTAL (SM_ROWSUM + 2 * BM * 4)          // 99328 (x2 CTAs <= 228KB)

// ============================================================================
// prep kernel: pure fp32 -> bf16 converts [weight | input]
// ============================================================================
__global__ void k_prep(const float* __restrict__ input, const float* __restrict__ weight,
                       int nb_w, long real8, long pad8, long n8) {
    const int blk = blockIdx.x;
    const int tid = threadIdx.x;

    if (blk < nb_w) {
        // ---- weight fp32 -> bf16 (zero-padded rows) ----
        long i = (long)blk * 256 + tid;
        if (i >= pad8) return;
        float4 v0 = make_float4(0.f, 0.f, 0.f, 0.f), v1 = v0;
        if (i < real8) {
            v0 = reinterpret_cast<const float4*>(weight)[i * 2];
            v1 = reinterpret_cast<const float4*>(weight)[i * 2 + 1];
        }
        uint4 o;
        o.x = pack_bf16x2(v0.x, v0.y);
        o.y = pack_bf16x2(v0.z, v0.w);
        o.z = pack_bf16x2(v1.x, v1.y);
        o.w = pack_bf16x2(v1.z, v1.w);
        reinterpret_cast<uint4*>(g_W)[i] = o;
    } else {
        // ---- input fp32 -> bf16 ----
        long i = (long)(blk - nb_w) * 256 + tid;
        if (i >= n8) return;
        const float4 v0 = reinterpret_cast<const float4*>(input)[i * 2];
        const float4 v1 = reinterpret_cast<const float4*>(input)[i * 2 + 1];
        uint4 o;
        o.x = pack_bf16x2(v0.x, v0.y);
        o.y = pack_bf16x2(v0.z, v0.w);
        o.z = pack_bf16x2(v1.x, v1.y);
        o.w = pack_bf16x2(v1.z, v1.w);
        reinterpret_cast<uint4*>(g_A)[i] = o;
    }
}

// ============================================================================
// GEMM (128x128 CTA tile, 4 warps, 2 CTAs/SM) + fused sum(exp(logit+bias))
// + target-logit extraction from accumulators (unique writer per token).
// ============================================================================
__global__ void __launch_bounds__(GEMM_THREADS, 2)
k_gemm_lse(const float* __restrict__ bias, const int* __restrict__ target,
           int Ntok, int D, int V) {
    extern __shared__ char smem[];
    const uint32_t sb = smem_to_u32(smem);
    const int tid = threadIdx.x;
    const int wid = tid >> 5;
    const int g   = tid & 31;
    const int mw  = wid >> 1;       // 0..1
    const int nw  = wid & 1;        // 0..1
    const int mbase = mw * 64;
    const int nbase = nw * 64;
    const int m0 = blockIdx.x * BM;
    const int vt = blockIdx.y;
    const int v0 = vt * BN;
    const int T = D / BK;           // 32

    // ---- hoisted load addressing ----
    const int ld_row = tid >> 3;                 // 0..15
    const int ld_c   = tid & 7;
    const __nv_bfloat16* aptr = g_A + (long)(m0 + ld_row) * D + ld_c * 8;
    const __nv_bfloat16* bptr = g_W + (long)(v0 + ld_row) * D + ld_c * 8;
    const long ld_stride = 16 * (long)D;
    const uint32_t ld_soff = (uint32_t)(ld_row * 128 + ((ld_c * 16) ^ ((ld_row & 7) << 4)));

    auto load_stage = [&](int s) {
        const uint32_t sa = sb + SM_A(s) + ld_soff;
        const uint32_t sB = sb + SM_B(s) + ld_soff;
        #pragma unroll
        for (int i = 0; i < 8; i++) cp_async16(sa + i * 2048, aptr + i * ld_stride);
        #pragma unroll
        for (int i = 0; i < 8; i++) cp_async16(sB + i * 2048, bptr + i * ld_stride);
    };

    float acc[4][8][4];
    #pragma unroll
    for (int mi = 0; mi < 4; mi++)
        #pragma unroll
        for (int ni = 0; ni < 8; ni++)
            #pragma unroll
            for (int j = 0; j < 4; j++) acc[mi][ni][j] = 0.f;

    const int a_row_lo = g & 15;
    const int a_kxor = (g >> 4) << 4;
    const int b_row_lo = ((g >> 4) << 3) + (g & 7);
    const int b_kxor = (g & 8) << 1;

    const uint32_t a_row_off = (uint32_t)((mbase + a_row_lo) * 128);
    const uint32_t b_row_off = (uint32_t)((nbase + b_row_lo) * 128);
    const uint32_t a_xorv = (uint32_t)(((mbase + a_row_lo) & 7) << 4);
    const uint32_t b_xorv = (uint32_t)(((nbase + b_row_lo) & 7) << 4);

    uint32_t a_kp[4], b_kp[4];
    #pragma unroll
    for (int ks = 0; ks < 4; ks++) {
        a_kp[ks] = (((uint32_t)(ks * 32) + (uint32_t)a_kxor) ^ a_xorv);
        b_kp[ks] = (((uint32_t)(ks * 32) + (uint32_t)b_kxor) ^ b_xorv);
    }

    #pragma unroll
    for (int s = 0; s < STAGES - 1; s++) { load_stage(s); CP_COMMIT(); aptr += BK; bptr += BK; }

    uint32_t a[2][4][4], b[2][4][4];   // ks double buffer

    for (int t = 0; t < T; t++) {
        CP_WAIT(1);
        __syncthreads();
        const int s = t % STAGES;
        const uint32_t abase = sb + SM_A(s) + a_row_off;
        const uint32_t bbase = sb + SM_B(s) + b_row_off;

        // prime ks=0 fragments FIRST (their stage is complete per CP_WAIT) ...
        #pragma unroll
        for (int mi = 0; mi < 4; mi++)
            ldsm_x4(a[0][mi][0], a[0][mi][1], a[0][mi][2], a[0][mi][3],
                    abase + mi * 2048 + a_kp[0]);
        #pragma unroll
        for (int np = 0; np < 4; np++)
            ldsm_x4(b[0][np][0], b[0][np][1], b[0][np][2], b[0][np][3],
                    bbase + np * 2048 + b_kp[0]);

        // ... then the cp.async burst drains under the ks=0/1 mma stream
        if (t + STAGES - 1 < T) { load_stage((t + STAGES - 1) % STAGES); aptr += BK; bptr += BK; }
        CP_COMMIT();

        #pragma unroll
        for (int ks = 0; ks < 4; ks++) {
            const int cur = ks & 1, nxt = cur ^ 1;
            if (ks < 3) {
                #pragma unroll
                for (int mi = 0; mi < 4; mi++)
                    ldsm_x4(a[nxt][mi][0], a[nxt][mi][1], a[nxt][mi][2], a[nxt][mi][3],
                            abase + mi * 2048 + a_kp[ks + 1]);
                #pragma unroll
                for (int np = 0; np < 4; np++)
                    ldsm_x4(b[nxt][np][0], b[nxt][np][1], b[nxt][np][2], b[nxt][np][3],
                            bbase + np * 2048 + b_kp[ks + 1]);
            }
            #pragma unroll
            for (int mi = 0; mi < 4; mi++)
                #pragma unroll
                for (int ni = 0; ni < 8; ni++)
                    mma_16816(acc[mi][ni], a[cur][mi], &b[cur][ni >> 1][(ni & 1) * 2]);
        }
    }
    __syncthreads();

    // ---- epilogue: per-row sum(exp(logit + bias)) + target-logit capture ----
    float* rowsum = reinterpret_cast<float*>(smem + SM_ROWSUM);
    if (v0 + BN <= V) {
        float bb[16];
        #pragma unroll
        for (int ni = 0; ni < 8; ni++) {
            int col = v0 + nbase + ni * 8 + (g & 3) * 2;
            bb[ni * 2]     = bias[col];
            bb[ni * 2 + 1] = bias[col + 1];
        }
        #pragma unroll
        for (int mi = 0; mi < 4; mi++) {
            const int r0g = m0 + mbase + mi * 16 + (g >> 2);
            const int r1g = r0g + 8;
            const int t0 = target[r0g];
            const int t1 = target[r1g];
            float s0 = 0.f, s1 = 0.f;
            #pragma unroll
            for (int ni = 0; ni < 8; ni++) {
                const int col = v0 + nbase + ni * 8 + (g & 3) * 2;
                s0 += __expf(acc[mi][ni][0] + bb[ni * 2]);
                s0 += __expf(acc[mi][ni][1] + bb[ni * 2 + 1]);
                s1 += __expf(acc[mi][ni][2] + bb[ni * 2]);
                s1 += __expf(acc[mi][ni][3] + bb[ni * 2 + 1]);
                // target-logit capture (unique matching thread across grid)
                if (t0 == col)     g_tgt[r0g] = acc[mi][ni][0] + bb[ni * 2];
                if (t0 == col + 1) g_tgt[r0g] = acc[mi][ni][1] + bb[ni * 2 + 1];
                if (t1 == col)     g_tgt[r1g] = acc[mi][ni][2] + bb[ni * 2];
                if (t1 == col + 1) g_tgt[r1g] = acc[mi][ni][3] + bb[ni * 2 + 1];
            }
            s0 += __shfl_xor_sync(0xffffffffu, s0, 1); s0 += __shfl_xor_sync(0xffffffffu, s0, 2);
            s1 += __shfl_xor_sync(0xffffffffu, s1, 1); s1 += __shfl_xor_sync(0xffffffffu, s1, 2);
            if ((g & 3) == 0) {
                int r = mbase + mi * 16 + (g >> 2);
                rowsum[nw * BM + r]     = s0;
                rowsum[nw * BM + r + 8] = s1;
            }
        }
    } else {
        #pragma unroll
        for (int mi = 0; mi < 4; mi++) {
            const int r0g = m0 + mbase + mi * 16 + (g >> 2);
            const int r1g = r0g + 8;
            const int t0 = target[r0g];
            const int t1 = target[r1g];
            float s0 = 0.f, s1 = 0.f;
            #pragma unroll
            for (int ni = 0; ni < 8; ni++) {
                int col = v0 + nbase + ni * 8 + (g & 3) * 2;
                float b0 = (col < V)     ? bias[col]     : 0.f;
                float b1 = (col + 1 < V) ? bias[col + 1] : 0.f;
                if (col < V)     { s0 += __expf(acc[mi][ni][0] + b0); s1 += __expf(acc[mi][ni][2] + b0); }
                if (col + 1 < V) { s0 += __expf(acc[mi][ni][1] + b1); s1 += __expf(acc[mi][ni][3] + b1); }
                if (t0 == col)     g_tgt[r0g] = acc[mi][ni][0] + b0;
                if (t0 == col + 1) g_tgt[r0g] = acc[mi][ni][1] + b1;
                if (t1 == col)     g_tgt[r1g] = acc[mi][ni][2] + b0;
                if (t1 == col + 1) g_tgt[r1g] = acc[mi][ni][3] + b1;
            }
            s0 += __shfl_xor_sync(0xffffffffu, s0, 1); s0 += __shfl_xor_sync(0xffffffffu, s0, 2);
            s1 += __shfl_xor_sync(0xffffffffu, s1, 1); s1 += __shfl_xor_sync(0xffffffffu, s1, 2);
            if ((g & 3) == 0) {
                int r = mbase + mi * 16 + (g >> 2);
                rowsum[nw * BM + r]     = s0;
                rowsum[nw * BM + r + 8] = s1;
            }
        }
    }
    __syncthreads();
    if (tid < BM) {
        float tot = rowsum[tid] + rowsum[BM + tid];
        g_part[(size_t)vt * Ntok + (m0 + tid)] = tot;
    }
}

// ============================================================================
// per-row reduce: lse, ce, z
// ============================================================================
__global__ void k_row_reduce(const int* __restrict__ target, int Ntok, int NVT, int V) {
    int r = blockIdx.x * blockDim.x + threadIdx.x;
    if (r >= Ntok) return;
    float s = 0.f;
    for (int i = 0; i < NVT; i++) s += g_part[(size_t)i * Ntok + r];
    float lse = logf(s);
    int t = target[r];
    bool valid = (t >= 0 && t < V);
    float z = LSE_SQ_SCALE * lse * lse;
    g_tok[r] = valid ? (lse - g_tgt[r] + z) : 0.f;
    g_zz[r]  = valid ? z : 0.f;
}

// ============================================================================
// final scalar reduce
// ============================================================================
__global__ void k_final(const int* __restrict__ target, float* __restrict__ out,
                        int Ntok, int V, int out_size) {
    __shared__ float s1[1024], s2[1024];
    __shared__ int s3[1024];
    int tid = threadIdx.x;
    float a = 0.f, b = 0.f; int c = 0;
    for (int i = tid; i < Ntok; i += blockDim.x) {
        a += g_tok[i];
        b += g_zz[i];
        int t = target[i];
        c += (t >= 0 && t < V) ? 1 : 0;
    }
    s1[tid] = a; s2[tid] = b; s3[tid] = c;
    __syncthreads();
    for (int o = blockDim.x >> 1; o; o >>= 1) {
        if (tid < o) { s1[tid] += s1[tid + o]; s2[tid] += s2[tid + o]; s3[tid] += s3[tid + o]; }
        __syncthreads();
    }
    if (tid == 0) {
        float nv = (float)(s3[0] > 0 ? s3[0] : 1);
        out[0] = s1[0] / nv;
        if (out_size > 1) out[1] = s2[0] / nv;
    }
}

// ============================================================================
extern "C" void kernel_launch(void* const* d_in, const int* in_sizes, int n_in,
                              void* d_out, int out_size) {
    const float* input = (const float*)d_in[0];
    const float* weight = (const float*)d_in[1];
    const float* bias = (const float*)d_in[2];
    const int* target = (const int*)d_in[3];

    const int V = in_sizes[2];
    const int Ntok = in_sizes[3];
    const int D = in_sizes[0] / Ntok;
    const int NVT = (V + BN - 1) / BN;     // 393
    const long Vpad = (long)NVT * BN;      // 50304

    // 1. prep: fp32 -> bf16 converts
    {
        long n8 = (long)Ntok * D / 8;
        long real8 = (long)V * D / 8;
        long pad8 = Vpad * D / 8;
        int nb_w = (int)((pad8 + 255) / 256);
        int nb_in = (int)((n8 + 255) / 256);
        k_prep<<<nb_w + nb_in, 256>>>(input, weight, nb_w, real8, pad8, n8);
    }

    // 2. GEMM + fused sum-exp + target-logit capture
    {
        cudaFuncSetAttribute(k_gemm_lse, cudaFuncAttributeMaxDynamicSharedMemorySize, SMEM_TOTAL);
        dim3 grid(Ntok / BM, NVT);
        k_gemm_lse<<<grid, GEMM_THREADS, SMEM_TOTAL>>>(bias, target, Ntok, D, V);
    }

    // 3. per-row reduce
    k_row_reduce<<<(Ntok + 127) / 128, 128>>>(target, Ntok, NVT, V);

    // 4. final scalars
    k_final<<<1, 1024>>>(target, (float*)d_out, Ntok, V, out_size);
}